// round 16
// baseline (speedup 1.0000x reference)
#include <cuda_runtime.h>
#include <cuda_bf16.h>
#include <cstdint>

#define BB   256
#define TT   512
#define II   300
#define HH   64
#define G3   192
#define KP   320      // K padded: 40 groups of 8
#define NTOT 384      // 192 fwd gates | 192 bwd gates
#define MTOT (BB * TT)
#define RING_D 8      // gru xp prefetch depth (steps)
#define NGRP 40       // k groups of 8

typedef unsigned long long ull;
typedef uint32_t u32;

__device__ float g_xp[2ull * TT * BB * G3];          // 201 MB scratch
__device__ float g_feat[BB * 256];
// Fragment-major tf32 operands:
// g_xtf[(rt*40 + G)*128 + lane*4 + v] : rt = row>>4 (8192), G = k>>3,
//   v = A-frag slot (r,c),(r+8,c),(r,c+4),(r+8,c+4)
__device__ float g_xtf[(size_t)(MTOT / 16) * NGRP * 128];   // 167.8 MB
// g_wtf[(ng*40 + G)*64 + lane*2 + h] : ng = n>>3, B-frag pairs (k=c, k=c+4)
__device__ float g_wtf[(NTOT / 8) * NGRP * 64];

// ---------------------------------------------------------------------------
// Helpers (plain sm_80+ features — valid on compute_103)
// ---------------------------------------------------------------------------
__device__ __forceinline__ u32 smem_u32(const void* p) {
    u32 a;
    asm("{ .reg .u64 t; cvta.to.shared.u64 t, %1; cvt.u32.u64 %0, t; }" : "=r"(a) : "l"(p));
    return a;
}
__device__ __forceinline__ void cp16(u32 dst, const void* src) {
    asm volatile("cp.async.cg.shared.global [%0], [%1], 16;" :: "r"(dst), "l"(src));
}
#define CP_COMMIT()  asm volatile("cp.async.commit_group;" ::: "memory")
#define CP_WAIT(n)   asm volatile("cp.async.wait_group %0;" :: "n"(n) : "memory")

__device__ __forceinline__ void mma_tf32(float* c, const u32* a, u32 b0, u32 b1) {
    asm volatile("mma.sync.aligned.m16n8k8.row.col.f32.tf32.tf32.f32 "
                 "{%0,%1,%2,%3}, {%4,%5,%6,%7}, {%8,%9}, {%0,%1,%2,%3};"
                 : "+f"(c[0]), "+f"(c[1]), "+f"(c[2]), "+f"(c[3])
                 : "r"(a[0]), "r"(a[1]), "r"(a[2]), "r"(a[3]), "r"(b0), "r"(b1));
}
// round fp32 -> tf32 (RNA, unbiased) stored back as fp32 bits
__device__ __forceinline__ float tf32r(float v) {
    u32 o; asm("cvt.rna.tf32.f32 %0, %1;" : "=r"(o) : "f"(v));
    return __uint_as_float(o);
}

// f32x2 (packed fp32 FFMA2) for the GRU
__device__ __forceinline__ ull ffma2(ull a, ull b, ull c) {
    ull d; asm("fma.rn.f32x2 %0, %1, %2, %3;" : "=l"(d) : "l"(a), "l"(b), "l"(c)); return d;
}
union F2U { ull u; float2 f; };
__device__ __forceinline__ float hsum2(ull a) { F2U t; t.u = a; return t.f.x + t.f.y; }

// ---------------------------------------------------------------------------
// Kernel 0a: W_ih (both dirs) -> tf32, B-fragment-major layout.
// ---------------------------------------------------------------------------
__global__ void __launch_bounds__(256)
wprep_kernel(const float* __restrict__ Wf, const float* __restrict__ Wb)
{
    const int task = blockIdx.x * 256 + threadIdx.x;   // 48*40*32 = 61440
    if (task >= (NTOT / 8) * NGRP * 32) return;
    const int lane = task & 31;
    const int G    = (task >> 5) % NGRP;
    const int ng   = task / (NGRP * 32);

    const int n = ng * 8 + (lane >> 2);
    const int k = G * 8 + (lane & 3);
    const float* W = (n < G3) ? Wf : Wb;
    const int nn = (n < G3) ? n : n - G3;

    float w0 = (k     < II) ? W[(size_t)nn * II + k]     : 0.f;
    float w1 = (k + 4 < II) ? W[(size_t)nn * II + k + 4] : 0.f;
    float2 o = make_float2(tf32r(w0), tf32r(w1));
    *(float2*)(g_wtf + ((size_t)ng * NGRP + G) * 64 + lane * 2) = o;
}

// ---------------------------------------------------------------------------
// Kernel 0b: x -> tf32, A-fragment-major layout.
// ---------------------------------------------------------------------------
__global__ void __launch_bounds__(256)
xprep_kernel(const float* __restrict__ x)
{
    const int task = blockIdx.x * 256 + threadIdx.x;   // 8192*40*32 tasks
    if (task >= (MTOT / 16) * NGRP * 32) return;
    const int lane = task & 31;
    const int G    = (task >> 5) % NGRP;
    const int rt   = task / (NGRP * 32);

    const int r = rt * 16 + (lane >> 2);
    const int k = G * 8 + (lane & 3);

    const float* xr0 = x + (size_t)r * II;
    const float* xr8 = xr0 + 8 * II;
    float v0 = 0.f, v1 = 0.f, v2 = 0.f, v3 = 0.f;
    if (k < II)     { v0 = xr0[k];     v1 = xr8[k]; }
    if (k + 4 < II) { v2 = xr0[k + 4]; v3 = xr8[k + 4]; }
    float4 o = make_float4(tf32r(v0), tf32r(v1), tf32r(v2), tf32r(v3));
    *(float4*)(g_xtf + ((size_t)rt * NGRP + G) * 128 + lane * 4) = o;
}

// ---------------------------------------------------------------------------
// Kernel 1: proj GEMM via single-pass tf32 mma.sync (m16n8k8).
// CTA tile 128(M) x 128(N), 8 warps 2m x 4n (warp tile 64x32), K-chunk 64,
// 2-stage cp.async. Fragment-major smem: A frag = 1 LDS.128, B frag = 1
// LDS.64 (conflict-free) — 8 LDS per 16 mma. Grid (3 N fastest, 1024 M).
// ---------------------------------------------------------------------------
#define STG_FLOATS 16384               // A 8192 floats + B 8192 floats
#define STG_BYTES  65536
#define PROJ_SMEM  (2 * STG_BYTES)     // 131072

__global__ void __launch_bounds__(256, 1)
proj_kernel(const float* __restrict__ bf_, const float* __restrict__ bb_)
{
    extern __shared__ float dsm[];
    const u32 smem_base = smem_u32(dsm);

    const int tid    = threadIdx.x;
    const int lane   = tid & 31;
    const int wid    = tid >> 5;
    const int warp_m = wid & 1;          // 0..1
    const int warp_n = wid >> 1;         // 0..3
    const int r0     = blockIdx.y * 128; // M tile
    const int n0     = blockIdx.x * 128; // N tile (fastest -> L2 A reuse)
    const int rt0    = r0 >> 4;
    const int ng0    = n0 >> 3;

    float acc[4][4][4];
    #pragma unroll
    for (int i = 0; i < 4; i++)
        #pragma unroll
        for (int j = 0; j < 4; j++)
            #pragma unroll
            for (int q = 0; q < 4; q++) acc[i][j][q] = 0.f;

    auto load_stage = [&](int stg, int c) {
        const u32 sbA = smem_base + stg * STG_BYTES;
        const u32 sbB = sbA + 32768;
        #pragma unroll
        for (int it = 0; it < 8; it++) {     // A: 2048 cp16
            const int t  = tid + it * 256;
            const int ln = t & 31, G = (t >> 5) & 7, rt = t >> 8;
            const u32 dst = sbA + (u32)(((rt * 8 + G) * 32 + ln) * 16);
            const float* src = g_xtf
                + ((size_t)(rt0 + rt) * NGRP + (c * 8 + G)) * 128 + ln * 4;
            cp16(dst, src);
        }
        #pragma unroll
        for (int it = 0; it < 8; it++) {     // B: 2048 cp16
            const int t  = tid + it * 256;
            const int lp = t & 15, G = (t >> 4) & 7, ng = t >> 7;
            const u32 dst = sbB + (u32)(((ng * 8 + G) * 16 + lp) * 16);
            const float* src = g_wtf
                + ((size_t)(ng0 + ng) * NGRP + (c * 8 + G)) * 64 + lp * 4;
            cp16(dst, src);
        }
    };

    load_stage(0, 0);
    CP_COMMIT();

    for (int c = 0; c < 5; c++) {
        if (c + 1 < 5) { load_stage((c + 1) & 1, c + 1); CP_COMMIT(); CP_WAIT(1); }
        else           { CP_WAIT(0); }
        __syncthreads();

        const float* As = dsm + (c & 1) * STG_FLOATS;
        const float* Bs = As + 8192;

        #pragma unroll
        for (int g = 0; g < 8; g++) {
            u32 a[4][4], b[4][2];
            #pragma unroll
            for (int mi = 0; mi < 4; mi++) {
                const int mt = warp_m * 4 + mi;
                float4 av = *(const float4*)(As + ((mt * 8 + g) * 32 + lane) * 4);
                a[mi][0] = __float_as_uint(av.x);
                a[mi][1] = __float_as_uint(av.y);
                a[mi][2] = __float_as_uint(av.z);
                a[mi][3] = __float_as_uint(av.w);
            }
            #pragma unroll
            for (int j = 0; j < 4; j++) {
                const int ng = warp_n * 4 + j;
                float2 bv = *(const float2*)(Bs + ((ng * 8 + g) * 32 + lane) * 2);
                b[j][0] = __float_as_uint(bv.x);
                b[j][1] = __float_as_uint(bv.y);
            }
            #pragma unroll
            for (int mi = 0; mi < 4; mi++)
                #pragma unroll
                for (int j = 0; j < 4; j++)
                    mma_tf32(acc[mi][j], a[mi], b[j][0], b[j][1]);
        }
        __syncthreads();
    }

    // ---- epilogue: bias + scatter to g_xp in scan order ----
    #pragma unroll
    for (int j = 0; j < 4; j++) {
        const int col = n0 + warp_n * 32 + j * 8 + (lane & 3) * 2;
        const int dir = (col >= G3) ? 1 : 0;
        const int g   = col - dir * G3;
        const float2 bv = *(const float2*)((dir ? bb_ : bf_) + g);
        #pragma unroll
        for (int mi = 0; mi < 4; mi++) {
            #pragma unroll
            for (int h = 0; h < 2; h++) {
                const int r = r0 + warp_m * 64 + mi * 16 + (lane >> 2) + h * 8;
                const int b = r >> 9, t = r & 511;
                const int s = dir ? (TT - 1 - t) : t;
                float2 o;
                o.x = acc[mi][j][2*h]   + bv.x;
                o.y = acc[mi][j][2*h+1] + bv.y;
                *(float2*)&g_xp[(((size_t)dir * TT + s) * BB + b) * G3 + g] = o;
            }
        }
    }
}

// ---------------------------------------------------------------------------
// Kernel 2: GRU recurrence — R7 config (proven best). 1 chain per 128-thread
// block, 4 blocks/SM, pair-split weights, depth-8 cp.async xp ring.
// ---------------------------------------------------------------------------
__device__ __forceinline__ float sigmoid_fast(float a) {
    return 1.f / (1.f + __expf(-a));
}
__device__ __forceinline__ float tanh_fast(float a) {
    float c = fminf(fmaxf(a, -20.f), 20.f);
    float e = __expf(2.f * c);
    return (e - 1.f) / (e + 1.f);
}

__global__ void __launch_bounds__(128, 4)
gru_kernel(const float* __restrict__ Whh_f, const float* __restrict__ bhh_f,
           const float* __restrict__ Whh_b, const float* __restrict__ bhh_b)
{
    __shared__ __align__(16) float sh_h[2][64];
    __shared__ __align__(16) float ring[RING_D][192];

    const int tid  = threadIdx.x;
    const int j    = tid >> 1;
    const int half = tid & 1;
    const int dir  = blockIdx.x >> 8;
    const int b    = blockIdx.x & 255;

    const float* W  = dir ? Whh_b : Whh_f;
    const float* bh = dir ? bhh_b : bhh_f;

    ull wr[16], wz[16], wn[16];
    {
        const ulonglong2* Rr = (const ulonglong2*)(W + (size_t)j * 64         + half * 32);
        const ulonglong2* Rz = (const ulonglong2*)(W + (size_t)(j + 64) * 64  + half * 32);
        const ulonglong2* Rn = (const ulonglong2*)(W + (size_t)(j + 128) * 64 + half * 32);
        #pragma unroll
        for (int q = 0; q < 8; q++) {
            ((ulonglong2*)wr)[q] = Rr[q];
            ((ulonglong2*)wz)[q] = Rz[q];
            ((ulonglong2*)wn)[q] = Rn[q];
        }
    }
    const float br = bh[j], bz = bh[j + 64], bn = bh[j + 128];

    if (tid < 64) sh_h[0][tid] = 0.f;
    float h_old = 0.f;

    const float* xp_b = g_xp + ((size_t)dir * TT * BB + b) * G3;
    const size_t stride = (size_t)BB * G3;
    const u32 ring_base = smem_u32(ring);

    #pragma unroll
    for (int d = 0; d < RING_D; d++) {
        if (tid < 48)
            cp16(ring_base + (u32)(d * 768 + tid * 16),
                 xp_b + (size_t)d * stride + tid * 4);
        CP_COMMIT();
    }
    CP_WAIT(RING_D - 1);
    __syncthreads();

    #pragma unroll 1
    for (int s = 0; s < TT; s++) {
        const int slot = s & (RING_D - 1);
        const float* xp = ring[slot];
        const float xr = xp[j];
        const float xz = xp[j + 64];
        const float xn = xp[j + 128];

        const int pp = s & 1;
        const ulonglong2* hp = (const ulonglong2*)&sh_h[pp][half * 32];
        ull ar = 0ull, az = 0ull, an = 0ull;
        #pragma unroll
        for (int q = 0; q < 8; q++) {
            ulonglong2 h2 = hp[q];
            ar = ffma2(wr[2*q],   h2.x, ar);
            az = ffma2(wz[2*q],   h2.x, az);
            an = ffma2(wn[2*q],   h2.x, an);
            ar = ffma2(wr[2*q+1], h2.y, ar);
            az = ffma2(wz[2*q+1], h2.y, az);
            an = ffma2(wn[2*q+1], h2.y, an);
        }
        float gr = hsum2(ar), gz = hsum2(az), gn = hsum2(an);
        gr += __shfl_xor_sync(0xffffffffu, gr, 1);
        gz += __shfl_xor_sync(0xffffffffu, gz, 1);
        gn += __shfl_xor_sync(0xffffffffu, gn, 1);
        gr += br; gz += bz; gn += bn;

        const float r = sigmoid_fast(xr + gr);
        const float z = sigmoid_fast(xz + gz);
        const float n = tanh_fast(xn + r * gn);
        const float hnew = (1.f - z) * n + z * h_old;
        h_old = hnew;

        if (half == 0) {
            sh_h[1 - pp][j] = hnew;
            if (s == 0)
                g_feat[b * 256 + (dir ? 192 : 0) + j] = hnew;
        }

        CP_WAIT(RING_D - 2);
        __syncthreads();

        if (tid < 48)
            cp16(ring_base + (u32)(slot * 768 + tid * 16),
                 xp_b + (size_t)((s + RING_D) & (TT - 1)) * stride + tid * 4);
        CP_COMMIT();
    }

    if (half == 0)
        g_feat[b * 256 + (dir ? 64 : 128) + j] = h_old;
}

// ---------------------------------------------------------------------------
// Kernel 3: head. 8 warps per block, one warp per batch row; 32 blocks.
// ---------------------------------------------------------------------------
__global__ void __launch_bounds__(256)
head_kernel(const float* __restrict__ W1, const float* __restrict__ b1,
            const float* __restrict__ W2, const float* __restrict__ b2,
            float* __restrict__ out)
{
    const int wid = threadIdx.x >> 5;
    const int j   = threadIdx.x & 31;
    const int b   = blockIdx.x * 8 + wid;
    const float* f = g_feat + b * 256;
    const float* w = W1 + (size_t)j * 256;

    float acc = b1[j];
    #pragma unroll 8
    for (int k = 0; k < 256; k += 4) {
        float4 fv = *(const float4*)(f + k);
        float4 wv = *(const float4*)(w + k);
        acc += fv.x * wv.x + fv.y * wv.y + fv.z * wv.z + fv.w * wv.w;
    }
    acc = (acc >= 0.f) ? acc : 0.01f * acc;
    float v = acc * W2[j];
    #pragma unroll
    for (int off = 16; off; off >>= 1)
        v += __shfl_down_sync(0xffffffffu, v, off);
    if (j == 0) out[b] = v + b2[0];
}

// ---------------------------------------------------------------------------
extern "C" void kernel_launch(void* const* d_in, const int* in_sizes, int n_in,
                              void* d_out, int out_size)
{
    const float* x      = (const float*)d_in[0];
    const float* W_ih_f = (const float*)d_in[1];
    const float* W_hh_f = (const float*)d_in[2];
    const float* b_ih_f = (const float*)d_in[3];
    const float* b_hh_f = (const float*)d_in[4];
    const float* W_ih_b = (const float*)d_in[5];
    const float* W_hh_b = (const float*)d_in[6];
    const float* b_ih_b = (const float*)d_in[7];
    const float* b_hh_b = (const float*)d_in[8];
    const float* W1     = (const float*)d_in[9];
    const float* b1     = (const float*)d_in[10];
    const float* W2     = (const float*)d_in[11];
    const float* b2     = (const float*)d_in[12];
    float* out = (float*)d_out;

    cudaFuncSetAttribute(proj_kernel, cudaFuncAttributeMaxDynamicSharedMemorySize, PROJ_SMEM);

    wprep_kernel<<<((NTOT / 8) * NGRP * 32 + 255) / 256, 256>>>(W_ih_f, W_ih_b);
    xprep_kernel<<<((MTOT / 16) * NGRP * 32 + 255) / 256, 256>>>(x);
    proj_kernel<<<dim3(3, 1024), 256, PROJ_SMEM>>>(b_ih_f, b_ih_b);
    gru_kernel<<<512, 128>>>(W_hh_f, b_hh_f, W_hh_b, b_hh_b);
    head_kernel<<<32, 256>>>(W1, b1, W2, b2, out);
}

// round 17
// speedup vs baseline: 1.4714x; 1.4714x over previous
#include <cuda_runtime.h>
#include <cuda_bf16.h>
#include <cstdint>

#define BB   256
#define TT   512
#define II   300
#define HH   64
#define G3   192
#define KP   320      // K padded: 5 chunks of 64
#define NTOT 384      // 192 fwd gates | 192 bwd gates
#define MTOT (BB * TT)
#define RING_D 8      // gru xp prefetch depth (steps)
#define ROWF 68       // smem floats per row (68 mod 32 = 4 -> conflict-free frags)

typedef unsigned long long ull;
typedef uint32_t u32;

__device__ float g_xp[2ull * TT * BB * G3];          // 201 MB scratch
__device__ float g_feat[BB * 256];
__device__ float g_xt[(size_t)MTOT * KP];            // 167 MB x in tf32 (padded)
__device__ float g_wt[NTOT * KP];                    // W in tf32 (padded, both dirs)

// ---------------------------------------------------------------------------
// Helpers (plain sm_80+ features — valid on compute_103)
// ---------------------------------------------------------------------------
__device__ __forceinline__ u32 smem_u32(const void* p) {
    u32 a;
    asm("{ .reg .u64 t; cvta.to.shared.u64 t, %1; cvt.u32.u64 %0, t; }" : "=r"(a) : "l"(p));
    return a;
}
__device__ __forceinline__ void cp16(u32 dst, const void* src) {
    asm volatile("cp.async.cg.shared.global [%0], [%1], 16;" :: "r"(dst), "l"(src));
}
#define CP_COMMIT()  asm volatile("cp.async.commit_group;" ::: "memory")
#define CP_WAIT(n)   asm volatile("cp.async.wait_group %0;" :: "n"(n) : "memory")

__device__ __forceinline__ void mma_tf32(float* c, const u32* a, u32 b0, u32 b1) {
    asm volatile("mma.sync.aligned.m16n8k8.row.col.f32.tf32.tf32.f32 "
                 "{%0,%1,%2,%3}, {%4,%5,%6,%7}, {%8,%9}, {%0,%1,%2,%3};"
                 : "+f"(c[0]), "+f"(c[1]), "+f"(c[2]), "+f"(c[3])
                 : "r"(a[0]), "r"(a[1]), "r"(a[2]), "r"(a[3]), "r"(b0), "r"(b1));
}
// round fp32 -> tf32 (RNA, unbiased) stored back as fp32 bits
__device__ __forceinline__ float tf32r(float v) {
    u32 o; asm("cvt.rna.tf32.f32 %0, %1;" : "=r"(o) : "f"(v));
    return __uint_as_float(o);
}

// f32x2 (packed fp32 FFMA2) for the GRU
__device__ __forceinline__ ull ffma2(ull a, ull b, ull c) {
    ull d; asm("fma.rn.f32x2 %0, %1, %2, %3;" : "=l"(d) : "l"(a), "l"(b), "l"(c)); return d;
}
union F2U { ull u; float2 f; };
__device__ __forceinline__ float hsum2(ull a) { F2U t; t.u = a; return t.f.x + t.f.y; }

// ---------------------------------------------------------------------------
// Kernel 0a: W_ih (both dirs) -> tf32-rounded fp32, K padded to 320.
// ---------------------------------------------------------------------------
__global__ void __launch_bounds__(256)
wprep_kernel(const float* __restrict__ Wf, const float* __restrict__ Wb)
{
    int i = blockIdx.x * 256 + threadIdx.x;
    if (i >= NTOT * KP) return;
    const int n = i / KP, k = i % KP;
    float v = 0.f;
    if (k < II) v = (n < G3) ? Wf[(size_t)n * II + k] : Wb[(size_t)(n - G3) * II + k];
    g_wt[i] = tf32r(v);
}

// ---------------------------------------------------------------------------
// Kernel 0b: x -> tf32-rounded fp32, K padded to 320. One thread = 8 cols.
// ---------------------------------------------------------------------------
__global__ void __launch_bounds__(256)
xprep_kernel(const float* __restrict__ x)
{
    const int task = blockIdx.x * 256 + threadIdx.x;   // MTOT*40 tasks
    if (task >= MTOT * 40) return;
    const int row = task / 40;
    const int c0  = (task % 40) * 8;

    const float* src = x + (size_t)row * II + c0;
    float4 v0 = make_float4(0.f, 0.f, 0.f, 0.f), v1 = v0;
    if (c0     <= 296) v0 = *(const float4*)src;
    if (c0 + 4 <= 296) v1 = *(const float4*)(src + 4);
    float4 o0, o1;
    o0.x = tf32r(v0.x); o0.y = tf32r(v0.y); o0.z = tf32r(v0.z); o0.w = tf32r(v0.w);
    o1.x = tf32r(v1.x); o1.y = tf32r(v1.y); o1.z = tf32r(v1.z); o1.w = tf32r(v1.w);
    const size_t di = (size_t)row * KP + c0;
    *(float4*)(g_xt + di)     = o0;
    *(float4*)(g_xt + di + 4) = o1;
}

// ---------------------------------------------------------------------------
// Kernel 1: proj GEMM via single-pass tf32 mma.sync (m16n8k8).
// CTA tile 128(M) x 128(N), 8 warps 2m x 4n (warp tile 64x32), K-chunk 64
// (8 k8 steps), 2-stage cp.async pipeline. Fragments via LDS.32 from rows
// padded to 68 floats (conflict-free). Grid (3 N fastest, 1024 M) -> L2 A reuse.
// ---------------------------------------------------------------------------
#define STG_FLOATS (256 * ROWF)            // A 128 rows + B 128 rows
#define STG_BYTES  (STG_FLOATS * 4)        // 69632
#define PROJ_SMEM  (2 * STG_BYTES)         // 139264

__global__ void __launch_bounds__(256, 1)
proj_kernel(const float* __restrict__ bf_, const float* __restrict__ bb_)
{
    extern __shared__ float dsm[];
    const u32 smem_base = smem_u32(dsm);

    const int tid    = threadIdx.x;
    const int lane   = tid & 31;
    const int wid    = tid >> 5;
    const int warp_m = wid & 1;          // 0..1
    const int warp_n = wid >> 1;         // 0..3
    const int r0     = blockIdx.y * 128; // M tile
    const int n0     = blockIdx.x * 128; // N tile (fastest -> L2 A reuse)

    float acc[4][4][4];
    #pragma unroll
    for (int i = 0; i < 4; i++)
        #pragma unroll
        for (int j = 0; j < 4; j++)
            #pragma unroll
            for (int q = 0; q < 4; q++) acc[i][j][q] = 0.f;

    // stage loader: 4096 cp16 (A 2048 | B 2048), 16 per thread
    auto load_stage = [&](int stg, int c) {
        const int k0 = c * 64;
        const u32 sb = smem_base + stg * STG_BYTES;
        #pragma unroll
        for (int it = 0; it < 16; it++) {
            const int t = tid + it * 256;
            const int side = t >> 11;            // 0 = A, 1 = B
            const int r = (t >> 4) & 127;
            const int q = t & 15;
            const u32 dst = sb + (u32)((side * 128 + r) * (ROWF * 4) + q * 16);
            const float* src = side
                ? g_wt + (size_t)(n0 + r) * KP + k0 + q * 4
                : g_xt + (size_t)(r0 + r) * KP + k0 + q * 4;
            cp16(dst, src);
        }
    };

    load_stage(0, 0);
    CP_COMMIT();

    const int rA = lane >> 2;   // 0..7
    const int cA = lane & 3;    // 0..3

    for (int c = 0; c < 5; c++) {
        if (c + 1 < 5) { load_stage((c + 1) & 1, c + 1); CP_COMMIT(); CP_WAIT(1); }
        else           { CP_WAIT(0); }
        __syncthreads();

        const float* As = dsm + (c & 1) * STG_FLOATS;
        const float* Bs = As + 128 * ROWF;

        #pragma unroll
        for (int g = 0; g < 8; g++) {
            u32 a[4][4], b[4][2];
            #pragma unroll
            for (int mi = 0; mi < 4; mi++) {
                const float* ap = As + (warp_m * 64 + mi * 16 + rA) * ROWF + g * 8 + cA;
                a[mi][0] = __float_as_uint(ap[0]);
                a[mi][1] = __float_as_uint(ap[8 * ROWF]);
                a[mi][2] = __float_as_uint(ap[4]);
                a[mi][3] = __float_as_uint(ap[8 * ROWF + 4]);
            }
            #pragma unroll
            for (int j = 0; j < 4; j++) {
                const float* bp = Bs + (warp_n * 32 + j * 8 + rA) * ROWF + g * 8 + cA;
                b[j][0] = __float_as_uint(bp[0]);
                b[j][1] = __float_as_uint(bp[4]);
            }
            #pragma unroll
            for (int mi = 0; mi < 4; mi++)
                #pragma unroll
                for (int j = 0; j < 4; j++)
                    mma_tf32(acc[mi][j], a[mi], b[j][0], b[j][1]);
        }
        __syncthreads();   // all warps done with this stage before it is refilled
    }

    // ---- epilogue: bias + scatter to g_xp in scan order ----
    #pragma unroll
    for (int j = 0; j < 4; j++) {
        const int col = n0 + warp_n * 32 + j * 8 + (lane & 3) * 2;
        const int dir = (col >= G3) ? 1 : 0;
        const int g   = col - dir * G3;
        const float2 bv = *(const float2*)((dir ? bb_ : bf_) + g);
        #pragma unroll
        for (int mi = 0; mi < 4; mi++) {
            #pragma unroll
            for (int h = 0; h < 2; h++) {
                const int r = r0 + warp_m * 64 + mi * 16 + (lane >> 2) + h * 8;
                const int b = r >> 9, t = r & 511;
                const int s = dir ? (TT - 1 - t) : t;
                float2 o;
                o.x = acc[mi][j][2*h]   + bv.x;
                o.y = acc[mi][j][2*h+1] + bv.y;
                *(float2*)&g_xp[(((size_t)dir * TT + s) * BB + b) * G3 + g] = o;
            }
        }
    }
}

// ---------------------------------------------------------------------------
// Kernel 2: GRU recurrence — R7 config (proven best). 1 chain per 128-thread
// block, 4 blocks/SM, pair-split weights, depth-8 cp.async xp ring.
// ---------------------------------------------------------------------------
__device__ __forceinline__ float sigmoid_fast(float a) {
    return 1.f / (1.f + __expf(-a));
}
__device__ __forceinline__ float tanh_fast(float a) {
    float c = fminf(fmaxf(a, -20.f), 20.f);
    float e = __expf(2.f * c);
    return (e - 1.f) / (e + 1.f);
}

__global__ void __launch_bounds__(128, 4)
gru_kernel(const float* __restrict__ Whh_f, const float* __restrict__ bhh_f,
           const float* __restrict__ Whh_b, const float* __restrict__ bhh_b)
{
    __shared__ __align__(16) float sh_h[2][64];
    __shared__ __align__(16) float ring[RING_D][192];

    const int tid  = threadIdx.x;
    const int j    = tid >> 1;
    const int half = tid & 1;
    const int dir  = blockIdx.x >> 8;
    const int b    = blockIdx.x & 255;

    const float* W  = dir ? Whh_b : Whh_f;
    const float* bh = dir ? bhh_b : bhh_f;

    ull wr[16], wz[16], wn[16];
    {
        const ulonglong2* Rr = (const ulonglong2*)(W + (size_t)j * 64         + half * 32);
        const ulonglong2* Rz = (const ulonglong2*)(W + (size_t)(j + 64) * 64  + half * 32);
        const ulonglong2* Rn = (const ulonglong2*)(W + (size_t)(j + 128) * 64 + half * 32);
        #pragma unroll
        for (int q = 0; q < 8; q++) {
            ((ulonglong2*)wr)[q] = Rr[q];
            ((ulonglong2*)wz)[q] = Rz[q];
            ((ulonglong2*)wn)[q] = Rn[q];
        }
    }
    const float br = bh[j], bz = bh[j + 64], bn = bh[j + 128];

    if (tid < 64) sh_h[0][tid] = 0.f;
    float h_old = 0.f;

    const float* xp_b = g_xp + ((size_t)dir * TT * BB + b) * G3;
    const size_t stride = (size_t)BB * G3;
    const u32 ring_base = smem_u32(ring);

    #pragma unroll
    for (int d = 0; d < RING_D; d++) {
        if (tid < 48)
            cp16(ring_base + (u32)(d * 768 + tid * 16),
                 xp_b + (size_t)d * stride + tid * 4);
        CP_COMMIT();
    }
    CP_WAIT(RING_D - 1);
    __syncthreads();

    #pragma unroll 1
    for (int s = 0; s < TT; s++) {
        const int slot = s & (RING_D - 1);
        const float* xp = ring[slot];
        const float xr = xp[j];
        const float xz = xp[j + 64];
        const float xn = xp[j + 128];

        const int pp = s & 1;
        const ulonglong2* hp = (const ulonglong2*)&sh_h[pp][half * 32];
        ull ar = 0ull, az = 0ull, an = 0ull;
        #pragma unroll
        for (int q = 0; q < 8; q++) {
            ulonglong2 h2 = hp[q];
            ar = ffma2(wr[2*q],   h2.x, ar);
            az = ffma2(wz[2*q],   h2.x, az);
            an = ffma2(wn[2*q],   h2.x, an);
            ar = ffma2(wr[2*q+1], h2.y, ar);
            az = ffma2(wz[2*q+1], h2.y, az);
            an = ffma2(wn[2*q+1], h2.y, an);
        }
        float gr = hsum2(ar), gz = hsum2(az), gn = hsum2(an);
        gr += __shfl_xor_sync(0xffffffffu, gr, 1);
        gz += __shfl_xor_sync(0xffffffffu, gz, 1);
        gn += __shfl_xor_sync(0xffffffffu, gn, 1);
        gr += br; gz += bz; gn += bn;

        const float r = sigmoid_fast(xr + gr);
        const float z = sigmoid_fast(xz + gz);
        const float n = tanh_fast(xn + r * gn);
        const float hnew = (1.f - z) * n + z * h_old;
        h_old = hnew;

        if (half == 0) {
            sh_h[1 - pp][j] = hnew;
            if (s == 0)
                g_feat[b * 256 + (dir ? 192 : 0) + j] = hnew;
        }

        CP_WAIT(RING_D - 2);
        __syncthreads();

        if (tid < 48)
            cp16(ring_base + (u32)(slot * 768 + tid * 16),
                 xp_b + (size_t)((s + RING_D) & (TT - 1)) * stride + tid * 4);
        CP_COMMIT();
    }

    if (half == 0)
        g_feat[b * 256 + (dir ? 64 : 128) + j] = h_old;
}

// ---------------------------------------------------------------------------
// Kernel 3: head. 8 warps per block, one warp per batch row; 32 blocks.
// ---------------------------------------------------------------------------
__global__ void __launch_bounds__(256)
head_kernel(const float* __restrict__ W1, const float* __restrict__ b1,
            const float* __restrict__ W2, const float* __restrict__ b2,
            float* __restrict__ out)
{
    const int wid = threadIdx.x >> 5;
    const int j   = threadIdx.x & 31;
    const int b   = blockIdx.x * 8 + wid;
    const float* f = g_feat + b * 256;
    const float* w = W1 + (size_t)j * 256;

    float acc = b1[j];
    #pragma unroll 8
    for (int k = 0; k < 256; k += 4) {
        float4 fv = *(const float4*)(f + k);
        float4 wv = *(const float4*)(w + k);
        acc += fv.x * wv.x + fv.y * wv.y + fv.z * wv.z + fv.w * wv.w;
    }
    acc = (acc >= 0.f) ? acc : 0.01f * acc;
    float v = acc * W2[j];
    #pragma unroll
    for (int off = 16; off; off >>= 1)
        v += __shfl_down_sync(0xffffffffu, v, off);
    if (j == 0) out[b] = v + b2[0];
}

// ---------------------------------------------------------------------------
extern "C" void kernel_launch(void* const* d_in, const int* in_sizes, int n_in,
                              void* d_out, int out_size)
{
    const float* x      = (const float*)d_in[0];
    const float* W_ih_f = (const float*)d_in[1];
    const float* W_hh_f = (const float*)d_in[2];
    const float* b_ih_f = (const float*)d_in[3];
    const float* b_hh_f = (const float*)d_in[4];
    const float* W_ih_b = (const float*)d_in[5];
    const float* W_hh_b = (const float*)d_in[6];
    const float* b_ih_b = (const float*)d_in[7];
    const float* b_hh_b = (const float*)d_in[8];
    const float* W1     = (const float*)d_in[9];
    const float* b1     = (const float*)d_in[10];
    const float* W2     = (const float*)d_in[11];
    const float* b2     = (const float*)d_in[12];
    float* out = (float*)d_out;

    cudaFuncSetAttribute(proj_kernel, cudaFuncAttributeMaxDynamicSharedMemorySize, PROJ_SMEM);

    wprep_kernel<<<(NTOT * KP + 255) / 256, 256>>>(W_ih_f, W_ih_b);
    xprep_kernel<<<(MTOT * 40 + 255) / 256, 256>>>(x);
    proj_kernel<<<dim3(3, 1024), 256, PROJ_SMEM>>>(b_ih_f, b_ih_b);
    gru_kernel<<<512, 128>>>(W_hh_f, b_hh_f, W_hh_b, b_hh_b);
    head_kernel<<<32, 256>>>(W1, b1, W2, b2, out);
}